// round 2
// baseline (speedup 1.0000x reference)
#include <cuda_runtime.h>

// Problem shapes (fixed by the dataset)
#define Bn 2
#define Vn 5
#define Cn 32
#define Hn 256
#define Wn 320
#define Dn 4
#define HWn (Hn*Wn)
#define NPTS (Bn*Dn*HWn)          // 655360
#define VAR_ELEMS (Bn*Cn*Dn*HWn)  // 20971520
#define TILES_PER_B (HWn/32)      // 2560
#define NWARPS (Bn*TILES_PER_B)   // 5120
#define WPB 4                     // warps per block

// rot(9) + trans(3) per (b, v) for v=1..Vn-1
__device__ float g_rt[Bn*Vn*12];
// feats transposed to [B, V, H*W, C] (channel-contiguous pixel lines)
__device__ float g_featsT[(size_t)Bn*Vn*HWn*Cn];

// ---------------------------------------------------------------------------
// Prep: combine projections, invert ref, compute per-view rot/trans
// ---------------------------------------------------------------------------
__device__ __forceinline__ void combine_f32(const float* p, float M[4][4]) {
    const float* E = p;
    const float* K = p + 16;
    for (int i = 0; i < 4; i++)
        for (int j = 0; j < 4; j++)
            M[i][j] = E[i*4 + j];
    for (int i = 0; i < 3; i++)
        for (int j = 0; j < 4; j++) {
            float s = 0.f;
            for (int k = 0; k < 3; k++) s += K[i*4 + k] * E[k*4 + j];
            M[i][j] = s;
        }
}

__device__ void inv4x4(const float A[4][4], double X[4][4]) {
    double a[4][8];
    for (int i = 0; i < 4; i++) {
        for (int j = 0; j < 4; j++) {
            a[i][j] = (double)A[i][j];
            a[i][j+4] = (i == j) ? 1.0 : 0.0;
        }
    }
    for (int col = 0; col < 4; col++) {
        int piv = col; double best = fabs(a[col][col]);
        for (int r = col+1; r < 4; r++) {
            double v = fabs(a[r][col]);
            if (v > best) { best = v; piv = r; }
        }
        if (piv != col)
            for (int j = 0; j < 8; j++) { double t = a[col][j]; a[col][j] = a[piv][j]; a[piv][j] = t; }
        double dd = 1.0 / a[col][col];
        for (int j = 0; j < 8; j++) a[col][j] *= dd;
        for (int r = 0; r < 4; r++) {
            if (r == col) continue;
            double f = a[r][col];
            for (int j = 0; j < 8; j++) a[r][j] -= f * a[col][j];
        }
    }
    for (int i = 0; i < 4; i++)
        for (int j = 0; j < 4; j++) X[i][j] = a[i][j+4];
}

__global__ void prep_kernel(const float* __restrict__ proj) {
    if (threadIdx.x != 0 || blockIdx.x != 0) return;
    for (int b = 0; b < Bn; b++) {
        float Pr[4][4];
        combine_f32(proj + (size_t)(b*Vn + 0) * 32, Pr);
        double inv[4][4];
        inv4x4(Pr, inv);
        for (int v = 1; v < Vn; v++) {
            float Ps[4][4];
            combine_f32(proj + (size_t)(b*Vn + v) * 32, Ps);
            float* o = g_rt + (b*Vn + v) * 12;
            for (int i = 0; i < 3; i++) {
                double r0 = 0, r1 = 0, r2 = 0, t = 0;
                for (int k = 0; k < 4; k++) {
                    double s = (double)Ps[i][k];
                    r0 += s * inv[k][0];
                    r1 += s * inv[k][1];
                    r2 += s * inv[k][2];
                    t  += s * inv[k][3];
                }
                o[i*3 + 0] = (float)r0;
                o[i*3 + 1] = (float)r1;
                o[i*3 + 2] = (float)r2;
                o[9 + i]   = (float)t;
            }
        }
    }
}

// ---------------------------------------------------------------------------
// Transpose feats [BV, C, HW] -> g_featsT [BV, HW, C], 32x32 smem tiles
// ---------------------------------------------------------------------------
__global__ void __launch_bounds__(256)
transpose_kernel(const float* __restrict__ feats) {
    __shared__ float tile[32][33];
    const int bv   = blockIdx.y;          // 0..B*V-1
    const int pix0 = blockIdx.x * 32;
    const int tx = threadIdx.x;           // 0..31
    const int ty = threadIdx.y;           // 0..7
    const float* src = feats + (size_t)bv * (Cn*HWn);
    #pragma unroll
    for (int r = 0; r < 4; r++) {
        int c = ty + r*8;
        tile[c][tx] = src[(size_t)c*HWn + pix0 + tx];
    }
    __syncthreads();
    float* dst = g_featsT + ((size_t)bv*HWn + pix0) * Cn;
    #pragma unroll
    for (int r = 0; r < 4; r++) {
        int p = ty + r*8;
        dst[p*Cn + tx] = tile[tx][p];
    }
}

// ---------------------------------------------------------------------------
// Main kernel: warp = (b, 32-pixel tile), loops d.
// Phase 1: lane = pixel, compute warp coords/weights -> smem
// Phase 2: lane = channel-pair, fused x-pair LDG.64 gathers + shfl combine
// ---------------------------------------------------------------------------
__global__ void __launch_bounds__(32*WPB)
hammer_kernel(const float* __restrict__ depthv,
              float* __restrict__ outv,
              float* __restrict__ outm)
{
    // per-warp buffers: 32 px * 34 words (8 words per view: off0,off1,wxA,wxB,wy0,wy1,pad2)
    __shared__ float s_coord[WPB][32*34];
    __shared__ float s_outb [WPB][32*34];
    __shared__ float s_rt[Bn*Vn*12];

    const int tid = threadIdx.x;
    if (tid < Bn*Vn*12) s_rt[tid] = g_rt[tid];
    __syncthreads();

    const int wid  = tid >> 5;
    const int lane = tid & 31;
    const int gw   = blockIdx.x * WPB + wid;     // 0..NWARPS-1
    const int b    = gw / TILES_PER_B;
    const int tile = gw - b * TILES_PER_B;
    const int pix0 = tile << 5;
    const int pix  = pix0 + lane;
    const float xf = (float)(pix % Wn);
    const float yf = (float)(pix / Wn);

    float* cbuf = s_coord[wid];
    float* obuf = s_outb[wid];
    int mcnt = 0;

    const int refbase = (b*Vn) * HWn;   // view 0, element base / Cn

    for (int d = 0; d < Dn; d++) {
        // ---- phase 1: per-lane (= per-pixel) coordinate setup ----
        const float dep = depthv[(b*Dn + d)*HWn + pix];
        #pragma unroll
        for (int vi = 0; vi < 4; vi++) {
            const float* M = &s_rt[(b*Vn + vi + 1)*12];
            float px = (M[0]*xf + M[1]*yf + M[2])*dep + M[9];
            float py = (M[3]*xf + M[4]*yf + M[5])*dep + M[10];
            float pz = (M[6]*xf + M[7]*yf + M[8])*dep + M[11];
            float gx = px / pz;
            float gy = py / pz;
            float fx0 = floorf(gx), fy0 = floorf(gy);
            float ax = gx - fx0,    ay = gy - fy0;
            int x0 = (int)fx0, y0 = (int)fy0;
            int x1 = x0 + 1,   y1 = y0 + 1;
            float wx0 = (x0 >= 0 && x0 < Wn) ? (1.f - ax) : 0.f;
            float wx1 = (x1 >= 0 && x1 < Wn) ? ax : 0.f;
            float wy0 = (y0 >= 0 && y0 < Hn) ? (1.f - ay) : 0.f;
            float wy1 = (y1 >= 0 && y1 < Hn) ? ay : 0.f;
            int pb = min(max(x0, 0), Wn - 2);
            float wxA = (x0 == pb)     ? wx0 : ((x1 == pb)     ? wx1 : 0.f);
            float wxB = (x1 == pb + 1) ? wx1 : ((x0 == pb + 1) ? wx0 : 0.f);
            int y0c = min(max(y0, 0), Hn - 1);
            int y1c = min(max(y1, 0), Hn - 1);
            int vbase = (b*Vn + vi + 1)*HWn;
            int off0 = (vbase + y0c*Wn + pb)*Cn;   // element offsets into g_featsT
            int off1 = (vbase + y1c*Wn + pb)*Cn;
            float* cp = cbuf + lane*34 + vi*8;
            cp[0] = __int_as_float(off0);
            cp[1] = __int_as_float(off1);
            cp[2] = wxA; cp[3] = wxB;
            cp[4] = wy0; cp[5] = wy1;
        }
        __syncwarp();

        // ---- phase 2: lane = channel-pair, loop pixels ----
        const int xsel = (lane >> 4);   // 0: x=pb side, 1: x=pb+1 side
        for (int p = 0; p < 32; p++) {
            const float* cp = cbuf + p*34;
            float2 rf = *((const float2*)(g_featsT + (size_t)(refbase + pix0 + p)*Cn) + (lane & 15));
            float sx = rf.x, sy = rf.y;
            float qx = rf.x*rf.x, qy = rf.y*rf.y;
            unsigned nzb = 0u;
            #pragma unroll
            for (int vi = 0; vi < 4; vi++) {
                const float* cv = cp + vi*8;
                float2 offs = *(const float2*)(cv);
                int off0 = __float_as_int(offs.x);
                int off1 = __float_as_int(offs.y);
                float wx  = cv[2 + xsel];
                float2 wyv = *(const float2*)(cv + 4);
                // lane i reads elements (2i, 2i+1) of the contiguous 64-elem x-pair
                float2 f0 = *((const float2*)(g_featsT + off0) + lane);
                float2 f1 = *((const float2*)(g_featsT + off1) + lane);
                float tx_ = wyv.x*f0.x + wyv.y*f1.x;
                float ty_ = wyv.x*f0.y + wyv.y*f1.y;
                float mx = wx*tx_;
                float my = wx*ty_;
                float vx = mx + __shfl_xor_sync(0xffffffffu, mx, 16);
                float vy = my + __shfl_xor_sync(0xffffffffu, my, 16);
                if ((vx != 0.f) || (vy != 0.f)) nzb |= (1u << vi);
                sx += vx; sy += vy;
                qx = fmaf(vx, vx, qx);
                qy = fmaf(vy, vy, qy);
            }
            unsigned nzall = __reduce_or_sync(0xffffffffu, nzb);
            if (lane == p) mcnt += __popc(nzall);
            float ex = sx*0.2f, ey = sy*0.2f;
            float vrx = fmaf(qx, 0.2f, -ex*ex);
            float vry = fmaf(qy, 0.2f, -ey*ey);
            if (lane < 16)
                *(float2*)(obuf + p*34 + 2*lane) = make_float2(vrx, vry);
        }
        __syncwarp();

        // ---- coalesced write-out of this d-slab ----
        const int obase = ((b*Cn)*Dn + d)*HWn + pix0 + lane;
        #pragma unroll 8
        for (int c = 0; c < Cn; c++) {
            outv[obase + c*(Dn*HWn)] = obuf[lane*34 + c];
        }
        __syncwarp();
    }

    outm[b*HWn + pix0 + lane] = (float)mcnt;
}

// ---------------------------------------------------------------------------
// Launch
// ---------------------------------------------------------------------------
extern "C" void kernel_launch(void* const* d_in, const int* in_sizes, int n_in,
                              void* d_out, int out_size)
{
    const float* feats  = (const float*)d_in[0];
    const float* proj   = (const float*)d_in[1];
    const float* depthv = (const float*)d_in[2];

    float* outv = (float*)d_out;
    float* outm = outv + VAR_ELEMS;

    transpose_kernel<<<dim3(HWn/32, Bn*Vn), dim3(32, 8)>>>(feats);
    prep_kernel<<<1, 1>>>(proj);
    hammer_kernel<<<NWARPS/WPB, 32*WPB>>>(depthv, outv, outm);
}

// round 4
// speedup vs baseline: 1.9851x; 1.9851x over previous
#include <cuda_runtime.h>
#include <cuda_fp16.h>

#define Bn 2
#define Vn 5
#define Cn 32
#define Hn 256
#define Wn 320
#define Dn 4
#define HWn (Hn*Wn)
#define VAR_ELEMS (Bn*Cn*Dn*HWn)  // 20971520

// rot(9) + trans(3) per (b, v) for v=1..Vn-1
__device__ float g_rt[Bn*Vn*12];
// feats transposed to [B, V, H*W, C] in fp16 (channel-contiguous pixel lines, 64B each)
__device__ __half2 g_fT[(size_t)Bn*Vn*HWn*(Cn/2)];

// ---------------------------------------------------------------------------
// Prep: combine projections, invert ref, per-view rot/trans (one block per b)
// ---------------------------------------------------------------------------
__device__ __forceinline__ void combine_f32(const float* p, float M[4][4]) {
    const float* E = p;
    const float* K = p + 16;
    for (int i = 0; i < 4; i++)
        for (int j = 0; j < 4; j++)
            M[i][j] = E[i*4 + j];
    for (int i = 0; i < 3; i++)
        for (int j = 0; j < 4; j++) {
            float s = 0.f;
            for (int k = 0; k < 3; k++) s += K[i*4 + k] * E[k*4 + j];
            M[i][j] = s;
        }
}

__device__ void inv4x4(const float A[4][4], double X[4][4]) {
    double a[4][8];
    for (int i = 0; i < 4; i++) {
        for (int j = 0; j < 4; j++) {
            a[i][j] = (double)A[i][j];
            a[i][j+4] = (i == j) ? 1.0 : 0.0;
        }
    }
    for (int col = 0; col < 4; col++) {
        int piv = col; double best = fabs(a[col][col]);
        for (int r = col+1; r < 4; r++) {
            double v = fabs(a[r][col]);
            if (v > best) { best = v; piv = r; }
        }
        if (piv != col)
            for (int j = 0; j < 8; j++) { double t = a[col][j]; a[col][j] = a[piv][j]; a[piv][j] = t; }
        double dd = 1.0 / a[col][col];
        for (int j = 0; j < 8; j++) a[col][j] *= dd;
        for (int r = 0; r < 4; r++) {
            if (r == col) continue;
            double f = a[r][col];
            for (int j = 0; j < 8; j++) a[r][j] -= f * a[col][j];
        }
    }
    for (int i = 0; i < 4; i++)
        for (int j = 0; j < 4; j++) X[i][j] = a[i][j+4];
}

__global__ void prep_kernel(const float* __restrict__ proj) {
    if (threadIdx.x != 0) return;
    const int b = blockIdx.x;
    float Pr[4][4];
    combine_f32(proj + (size_t)(b*Vn + 0) * 32, Pr);
    double inv[4][4];
    inv4x4(Pr, inv);
    for (int v = 1; v < Vn; v++) {
        float Ps[4][4];
        combine_f32(proj + (size_t)(b*Vn + v) * 32, Ps);
        float* o = g_rt + (b*Vn + v) * 12;
        for (int i = 0; i < 3; i++) {
            double r0 = 0, r1 = 0, r2 = 0, t = 0;
            for (int k = 0; k < 4; k++) {
                double s = (double)Ps[i][k];
                r0 += s * inv[k][0];
                r1 += s * inv[k][1];
                r2 += s * inv[k][2];
                t  += s * inv[k][3];
            }
            o[i*3 + 0] = (float)r0;
            o[i*3 + 1] = (float)r1;
            o[i*3 + 2] = (float)r2;
            o[9 + i]   = (float)t;
        }
    }
}

// ---------------------------------------------------------------------------
// Transpose+convert: feats [BV, C, HW] f32 -> g_fT [BV, HW, C] fp16
// ---------------------------------------------------------------------------
__global__ void __launch_bounds__(256)
transpose_kernel(const float* __restrict__ feats) {
    __shared__ float tile[32][33];
    const int bv   = blockIdx.y;
    const int pix0 = blockIdx.x * 32;
    const int tx = threadIdx.x;   // 0..31
    const int ty = threadIdx.y;   // 0..7
    const float* src = feats + (size_t)bv * (Cn*HWn);
    #pragma unroll
    for (int r = 0; r < 4; r++) {
        int c = ty + r*8;
        tile[c][tx] = src[(size_t)c*HWn + pix0 + tx];
    }
    __syncthreads();
    const int t  = ty*32 + tx;
    const int c2 = t & 15;        // half2 index within pixel line
    const int pl = t >> 4;        // 0..15
    __half2* dst = g_fT + ((size_t)bv*HWn + pix0) * 16;
    #pragma unroll
    for (int r = 0; r < 2; r++) {
        int p = pl + r*16;
        dst[p*16 + c2] = __floats2half2_rn(tile[2*c2][p], tile[2*c2 + 1][p]);
    }
}

// ---------------------------------------------------------------------------
// Main kernel: thread = (b, pixel, cc); cc owns channels [cc*8, cc*8+8).
// Warp = 8 adjacent pixels x 4 cc-lanes. Straight-line gathers, full MLP.
// ---------------------------------------------------------------------------
__device__ __forceinline__ void up8(uint4 u, float* f) {
    float2 a;
    a = __half22float2(*(__half2*)&u.x); f[0] = a.x; f[1] = a.y;
    a = __half22float2(*(__half2*)&u.y); f[2] = a.x; f[3] = a.y;
    a = __half22float2(*(__half2*)&u.z); f[4] = a.x; f[5] = a.y;
    a = __half22float2(*(__half2*)&u.w); f[6] = a.x; f[7] = a.y;
}

__global__ void __launch_bounds__(256)
hammer_kernel(const float* __restrict__ depthv,
              float* __restrict__ outv,
              float* __restrict__ outm)
{
    __shared__ float s_rt[Bn*Vn*12];
    const int t = threadIdx.x;
    if (t < Bn*Vn*12) s_rt[t] = g_rt[t];
    __syncthreads();

    const int gid = blockIdx.x*256 + t;
    const int cc  = gid & 3;
    const int pg  = gid >> 2;          // 0..Bn*HWn-1
    const int b   = pg / HWn;
    const int pix = pg - b*HWn;
    const float xf = (float)(pix % Wn);
    const float yf = (float)(pix / Wn);

    // reference view: d-invariant, load once
    float rv[8];
    {
        uint4 ru = *(const uint4*)(g_fT + ((size_t)(b*Vn)*HWn + pix)*16 + cc*4);
        up8(ru, rv);
    }

    // hoist per-view row dots (depth-independent)
    float Ar[4], Br[4], Cr[4];
    #pragma unroll
    for (int vi = 0; vi < 4; vi++) {
        const float* M = &s_rt[(b*Vn + vi + 1)*12];
        Ar[vi] = fmaf(M[0], xf, fmaf(M[1], yf, M[2]));
        Br[vi] = fmaf(M[3], xf, fmaf(M[4], yf, M[5]));
        Cr[vi] = fmaf(M[6], xf, fmaf(M[7], yf, M[8]));
    }

    int mcnt = 0;

    #pragma unroll
    for (int d = 0; d < Dn; d++) {
        const float dep = depthv[(b*Dn + d)*HWn + pix];
        float s8[8], q8[8];
        #pragma unroll
        for (int j = 0; j < 8; j++) { s8[j] = rv[j]; q8[j] = rv[j]*rv[j]; }
        unsigned nzb = 0u;

        #pragma unroll
        for (int vi = 0; vi < 4; vi++) {
            const float* M = &s_rt[(b*Vn + vi + 1)*12];
            float pxv = fmaf(Ar[vi], dep, M[9]);
            float pyv = fmaf(Br[vi], dep, M[10]);
            float pzv = fmaf(Cr[vi], dep, M[11]);
            float rz = __frcp_rn(pzv);
            float gx = pxv * rz;
            float gy = pyv * rz;

            float fx0 = floorf(gx), fy0 = floorf(gy);
            float ax = gx - fx0,    ay = gy - fy0;
            int x0 = (int)fx0, y0 = (int)fy0;
            int x1 = x0 + 1,   y1 = y0 + 1;
            float wx0 = (x0 >= 0 && x0 < Wn) ? (1.f - ax) : 0.f;
            float wx1 = (x1 >= 0 && x1 < Wn) ? ax : 0.f;
            float wy0 = (y0 >= 0 && y0 < Hn) ? (1.f - ay) : 0.f;
            float wy1 = (y1 >= 0 && y1 < Hn) ? ay : 0.f;
            int pb = min(max(x0, 0), Wn - 2);
            float wxA = (x0 == pb)     ? wx0 : ((x1 == pb)     ? wx1 : 0.f);
            float wxB = (x1 == pb + 1) ? wx1 : ((x0 == pb + 1) ? wx0 : 0.f);
            int y0c = min(max(y0, 0), Hn - 1);
            int y1c = min(max(y1, 0), Hn - 1);

            const int vbase = (b*Vn + vi + 1)*HWn;
            const __half2* r0 = g_fT + (size_t)(vbase + y0c*Wn + pb)*16 + cc*4;
            const __half2* r1 = g_fT + (size_t)(vbase + y1c*Wn + pb)*16 + cc*4;
            uint4 u00 = *(const uint4*)r0;
            uint4 u01 = *(const uint4*)(r0 + 16);
            uint4 u10 = *(const uint4*)r1;
            uint4 u11 = *(const uint4*)(r1 + 16);
            float f00[8], f01[8], f10[8], f11[8];
            up8(u00, f00); up8(u01, f01); up8(u10, f10); up8(u11, f11);

            float sab = 0.f;
            #pragma unroll
            for (int j = 0; j < 8; j++) {
                float ra  = fmaf(wxB, f01[j], wxA*f00[j]);
                float rb  = fmaf(wxB, f11[j], wxA*f10[j]);
                float val = fmaf(wy1, rb, wy0*ra);
                sab += fabsf(val);
                s8[j] += val;
                q8[j] = fmaf(val, val, q8[j]);
            }
            if (sab != 0.f) nzb |= (1u << vi);
        }

        // any-channel-nonzero per view: OR across the 4 cc-lanes of this pixel
        nzb |= __shfl_xor_sync(0xffffffffu, nzb, 1);
        nzb |= __shfl_xor_sync(0xffffffffu, nzb, 2);
        mcnt += __popc(nzb);

        const int ob = ((b*Cn + cc*8)*Dn + d)*HWn + pix;
        #pragma unroll
        for (int j = 0; j < 8; j++) {
            float e = s8[j] * 0.2f;
            outv[ob + j*(Dn*HWn)] = fmaf(q8[j], 0.2f, -e*e);
        }
    }

    if (cc == 0) outm[b*HWn + pix] = (float)mcnt;
}

// ---------------------------------------------------------------------------
// Launch
// ---------------------------------------------------------------------------
extern "C" void kernel_launch(void* const* d_in, const int* in_sizes, int n_in,
                              void* d_out, int out_size)
{
    const float* feats  = (const float*)d_in[0];
    const float* proj   = (const float*)d_in[1];
    const float* depthv = (const float*)d_in[2];

    float* outv = (float*)d_out;
    float* outm = outv + VAR_ELEMS;

    prep_kernel<<<Bn, 32>>>(proj);
    transpose_kernel<<<dim3(HWn/32, Bn*Vn), dim3(32, 8)>>>(feats);
    hammer_kernel<<<(Bn*HWn*4)/256, 256>>>(depthv, outv, outm);
}

// round 5
// speedup vs baseline: 2.5430x; 1.2810x over previous
#include <cuda_runtime.h>
#include <cuda_fp16.h>

#define Bn 2
#define Vn 5
#define Cn 32
#define Hn 256
#define Wn 320
#define Dn 4
#define HWn (Hn*Wn)
#define VAR_ELEMS (Bn*Cn*Dn*HWn)  // 20971520

// rot(9) + trans(3) per (b, v) for v=1..Vn-1
__device__ float g_rt[Bn*Vn*12];
// feats transposed to [B, V, H*W, C] in fp16 (channel-contiguous 64B pixel lines)
__device__ __half2 g_fT[(size_t)Bn*Vn*HWn*(Cn/2)];

// ---------------------------------------------------------------------------
// Prep: combine projections; fast structured inverse (bottom row = 0,0,0,1)
// ---------------------------------------------------------------------------
__device__ __forceinline__ void combine_f32(const float* p, float M[4][4]) {
    const float* E = p;
    const float* K = p + 16;
    for (int i = 0; i < 4; i++)
        for (int j = 0; j < 4; j++)
            M[i][j] = E[i*4 + j];
    for (int i = 0; i < 3; i++)
        for (int j = 0; j < 4; j++) {
            float s = 0.f;
            for (int k = 0; k < 3; k++) s += K[i*4 + k] * E[k*4 + j];
            M[i][j] = s;
        }
}

__global__ void prep_kernel(const float* __restrict__ proj) {
    if (threadIdx.x != 0) return;
    const int b = blockIdx.x;

    float Pr[4][4];
    combine_f32(proj + (size_t)(b*Vn + 0) * 32, Pr);

    // 3x3 adjugate inverse in double (ref_proj bottom row is (0,0,0,1))
    double m00 = Pr[0][0], m01 = Pr[0][1], m02 = Pr[0][2];
    double m10 = Pr[1][0], m11 = Pr[1][1], m12 = Pr[1][2];
    double m20 = Pr[2][0], m21 = Pr[2][1], m22 = Pr[2][2];
    double t0  = Pr[0][3], t1  = Pr[1][3], t2  = Pr[2][3];

    double c00 = m11*m22 - m12*m21;
    double c01 = m12*m20 - m10*m22;
    double c02 = m10*m21 - m11*m20;
    double det = m00*c00 + m01*c01 + m02*c02;
    double id  = 1.0 / det;

    double inv3[3][3];
    inv3[0][0] = c00*id; inv3[0][1] = (m02*m21 - m01*m22)*id; inv3[0][2] = (m01*m12 - m02*m11)*id;
    inv3[1][0] = c01*id; inv3[1][1] = (m00*m22 - m02*m20)*id; inv3[1][2] = (m02*m10 - m00*m12)*id;
    inv3[2][0] = c02*id; inv3[2][1] = (m01*m20 - m00*m21)*id; inv3[2][2] = (m00*m11 - m01*m10)*id;

    double it[3];
    for (int k = 0; k < 3; k++)
        it[k] = -(inv3[k][0]*t0 + inv3[k][1]*t1 + inv3[k][2]*t2);

    for (int v = 1; v < Vn; v++) {
        float Ps[4][4];
        combine_f32(proj + (size_t)(b*Vn + v) * 32, Ps);
        float* o = g_rt + (b*Vn + v) * 12;
        for (int i = 0; i < 3; i++) {
            double r0 = 0, r1 = 0, r2 = 0, t = (double)Ps[i][3];
            for (int k = 0; k < 3; k++) {
                double s = (double)Ps[i][k];
                r0 += s * inv3[k][0];
                r1 += s * inv3[k][1];
                r2 += s * inv3[k][2];
                t  += s * it[k];
            }
            o[i*3 + 0] = (float)r0;
            o[i*3 + 1] = (float)r1;
            o[i*3 + 2] = (float)r2;
            o[9 + i]   = (float)t;
        }
    }
}

// ---------------------------------------------------------------------------
// Transpose+convert: feats [BV, C, HW] f32 -> g_fT [BV, HW, C] fp16
// 64-pixel tiles, float4 reads, uint4 (8-half) writes.
// ---------------------------------------------------------------------------
__global__ void __launch_bounds__(256)
transpose_kernel(const float* __restrict__ feats) {
    __shared__ float tile[32][65];
    const int bv   = blockIdx.y;
    const int pix0 = blockIdx.x * 64;
    const int tid = threadIdx.x;
    const int tx = tid & 15;      // pixel-quad 0..15 (4 px each)
    const int ty = tid >> 4;      // 0..15

    const float* src = feats + (size_t)bv * (Cn*HWn);
    #pragma unroll
    for (int r = 0; r < 2; r++) {
        int ch = ty + 16*r;
        float4 v = *(const float4*)(src + (size_t)ch*HWn + pix0 + tx*4);
        tile[ch][tx*4 + 0] = v.x;
        tile[ch][tx*4 + 1] = v.y;
        tile[ch][tx*4 + 2] = v.z;
        tile[ch][tx*4 + 3] = v.w;
    }
    __syncthreads();

    const int p = tid >> 2;       // pixel 0..63
    const int q = tid & 3;        // channel-quarter
    __half2 h[4];
    #pragma unroll
    for (int k = 0; k < 4; k++) {
        int c = q*8 + 2*k;
        h[k] = __floats2half2_rn(tile[c][p], tile[c+1][p]);
    }
    uint4 pk = make_uint4(*(unsigned*)&h[0], *(unsigned*)&h[1],
                          *(unsigned*)&h[2], *(unsigned*)&h[3]);
    uint4* dst = (uint4*)(g_fT + ((size_t)bv*HWn + pix0) * 16);
    dst[p*4 + q] = pk;
}

// ---------------------------------------------------------------------------
// Main kernel: thread = (b, pixel, cc); cc owns channels [cc*8, cc*8+8).
// half2 bilinear blend, f32 accumulation. Mask from weights.
// ---------------------------------------------------------------------------
__global__ void __launch_bounds__(256, 3)
hammer_kernel(const float* __restrict__ depthv,
              float* __restrict__ outv,
              float* __restrict__ outm)
{
    __shared__ float s_rt[Bn*Vn*12];
    const int t = threadIdx.x;
    if (t < Bn*Vn*12) s_rt[t] = g_rt[t];
    __syncthreads();

    const int gid = blockIdx.x*256 + t;
    const int cc  = gid & 3;
    const int pg  = gid >> 2;          // 0..Bn*HWn-1
    const int b   = pg / HWn;
    const int pix = pg - b*HWn;
    const float xf = (float)(pix % Wn);
    const float yf = (float)(pix / Wn);

    // reference view: d-invariant, load once, convert to f32
    float rv[8];
    {
        uint4 ru = *(const uint4*)(g_fT + ((size_t)(b*Vn)*HWn + pix)*16 + cc*4);
        const __half2* hp = (const __half2*)&ru;
        #pragma unroll
        for (int k = 0; k < 4; k++) {
            float2 a = __half22float2(hp[k]);
            rv[2*k]   = a.x;
            rv[2*k+1] = a.y;
        }
    }

    // per-view row dots (depth-independent)
    float Ar[4], Br[4], Cr[4];
    #pragma unroll
    for (int vi = 0; vi < 4; vi++) {
        const float* M = &s_rt[(b*Vn + vi + 1)*12];
        Ar[vi] = fmaf(M[0], xf, fmaf(M[1], yf, M[2]));
        Br[vi] = fmaf(M[3], xf, fmaf(M[4], yf, M[5]));
        Cr[vi] = fmaf(M[6], xf, fmaf(M[7], yf, M[8]));
    }

    int mcnt = 0;

    #pragma unroll 1
    for (int d = 0; d < Dn; d++) {
        const float dep = depthv[(b*Dn + d)*HWn + pix];
        float s8[8], q8[8];
        #pragma unroll
        for (int j = 0; j < 8; j++) { s8[j] = rv[j]; q8[j] = rv[j]*rv[j]; }

        #pragma unroll
        for (int vi = 0; vi < 4; vi++) {
            const float* M = &s_rt[(b*Vn + vi + 1)*12];
            float pxv = fmaf(Ar[vi], dep, M[9]);
            float pyv = fmaf(Br[vi], dep, M[10]);
            float pzv = fmaf(Cr[vi], dep, M[11]);
            float rz = __frcp_rn(pzv);
            float gx = pxv * rz;
            float gy = pyv * rz;

            float fx0 = floorf(gx), fy0 = floorf(gy);
            float ax = gx - fx0,    ay = gy - fy0;
            int x0 = (int)fx0, y0 = (int)fy0;
            int x1 = x0 + 1,   y1 = y0 + 1;
            float wx0 = (x0 >= 0 && x0 < Wn) ? (1.f - ax) : 0.f;
            float wx1 = (x1 >= 0 && x1 < Wn) ? ax : 0.f;
            float wy0 = (y0 >= 0 && y0 < Hn) ? (1.f - ay) : 0.f;
            float wy1 = (y1 >= 0 && y1 < Hn) ? ay : 0.f;

            // mask: any corner weight nonzero <=> x-side and y-side both reachable
            if (((wx0 + wx1) * (wy0 + wy1)) != 0.f) mcnt++;

            int pb = min(max(x0, 0), Wn - 2);
            float wxA = (x0 == pb)     ? wx0 : ((x1 == pb)     ? wx1 : 0.f);
            float wxB = (x1 == pb + 1) ? wx1 : ((x0 == pb + 1) ? wx0 : 0.f);
            int y0c = min(max(y0, 0), Hn - 1);
            int y1c = min(max(y1, 0), Hn - 1);

            const int vbase = (b*Vn + vi + 1)*HWn;
            const __half2* r0 = g_fT + (size_t)(vbase + y0c*Wn + pb)*16 + cc*4;
            const __half2* r1 = g_fT + (size_t)(vbase + y1c*Wn + pb)*16 + cc*4;
            uint4 u00 = *(const uint4*)r0;
            uint4 u01 = *(const uint4*)(r0 + 16);
            uint4 u10 = *(const uint4*)r1;
            uint4 u11 = *(const uint4*)(r1 + 16);

            __half2 wxA2 = __float2half2_rn(wxA);
            __half2 wxB2 = __float2half2_rn(wxB);
            __half2 wy02 = __float2half2_rn(wy0);
            __half2 wy12 = __float2half2_rn(wy1);

            const __half2* h00 = (const __half2*)&u00;
            const __half2* h01 = (const __half2*)&u01;
            const __half2* h10 = (const __half2*)&u10;
            const __half2* h11 = (const __half2*)&u11;

            #pragma unroll
            for (int k = 0; k < 4; k++) {
                __half2 ra = __hfma2(wxB2, h01[k], __hmul2(wxA2, h00[k]));
                __half2 rb = __hfma2(wxB2, h11[k], __hmul2(wxA2, h10[k]));
                __half2 v2 = __hfma2(wy12, rb, __hmul2(wy02, ra));
                float2 vf = __half22float2(v2);
                s8[2*k]   += vf.x;
                s8[2*k+1] += vf.y;
                q8[2*k]   = fmaf(vf.x, vf.x, q8[2*k]);
                q8[2*k+1] = fmaf(vf.y, vf.y, q8[2*k+1]);
            }
        }

        const int ob = ((b*Cn + cc*8)*Dn + d)*HWn + pix;
        #pragma unroll
        for (int j = 0; j < 8; j++) {
            float e = s8[j] * 0.2f;
            outv[ob + j*(Dn*HWn)] = fmaf(q8[j], 0.2f, -e*e);
        }
    }

    if (cc == 0) outm[b*HWn + pix] = (float)mcnt;
}

// ---------------------------------------------------------------------------
// Launch
// ---------------------------------------------------------------------------
extern "C" void kernel_launch(void* const* d_in, const int* in_sizes, int n_in,
                              void* d_out, int out_size)
{
    const float* feats  = (const float*)d_in[0];
    const float* proj   = (const float*)d_in[1];
    const float* depthv = (const float*)d_in[2];

    float* outv = (float*)d_out;
    float* outm = outv + VAR_ELEMS;

    prep_kernel<<<Bn, 32>>>(proj);
    transpose_kernel<<<dim3(HWn/64, Bn*Vn), 256>>>(feats);
    hammer_kernel<<<(Bn*HWn*4)/256, 256>>>(depthv, outv, outm);
}

// round 6
// speedup vs baseline: 2.8122x; 1.1059x over previous
#include <cuda_runtime.h>
#include <cuda_fp16.h>

#define Bn 2
#define Vn 5
#define Cn 32
#define Hn 256
#define Wn 320
#define Dn 4
#define HWn (Hn*Wn)
#define VAR_ELEMS (Bn*Cn*Dn*HWn)  // 20971520

// rot(9) + trans(3) per (b, v) for v=1..Vn-1
__device__ float g_rt[Bn*Vn*12];
// feats transposed to [B, V, H*W, C] in fp16 (channel-contiguous 64B pixel lines)
__device__ __half2 g_fT[(size_t)Bn*Vn*HWn*(Cn/2)];

// ---------------------------------------------------------------------------
// Prep (device-side, lane-parallel): combine projections, structured inverse
// ---------------------------------------------------------------------------
__device__ __forceinline__ void combine_f32(const float* p, float M[4][4]) {
    const float* E = p;
    const float* K = p + 16;
    #pragma unroll
    for (int i = 0; i < 4; i++)
        #pragma unroll
        for (int j = 0; j < 4; j++)
            M[i][j] = E[i*4 + j];
    #pragma unroll
    for (int i = 0; i < 3; i++)
        #pragma unroll
        for (int j = 0; j < 4; j++) {
            float s = 0.f;
            #pragma unroll
            for (int k = 0; k < 3; k++) s += K[i*4 + k] * E[k*4 + j];
            M[i][j] = s;
        }
}

// lane l in 0..Bn*(Vn-1)-1 computes rot/trans for (b = l/(Vn-1), v = l%(Vn-1)+1)
__device__ void prep_lane(const float* __restrict__ proj, int l) {
    const int b = l / (Vn - 1);
    const int v = (l % (Vn - 1)) + 1;

    float Pr[4][4];
    combine_f32(proj + (size_t)(b*Vn + 0) * 32, Pr);

    // 3x3 adjugate inverse in double (ref_proj bottom row is (0,0,0,1))
    double m00 = Pr[0][0], m01 = Pr[0][1], m02 = Pr[0][2];
    double m10 = Pr[1][0], m11 = Pr[1][1], m12 = Pr[1][2];
    double m20 = Pr[2][0], m21 = Pr[2][1], m22 = Pr[2][2];
    double t0  = Pr[0][3], t1  = Pr[1][3], t2  = Pr[2][3];

    double c00 = m11*m22 - m12*m21;
    double c01 = m12*m20 - m10*m22;
    double c02 = m10*m21 - m11*m20;
    double det = m00*c00 + m01*c01 + m02*c02;
    double id  = 1.0 / det;

    double inv3[3][3];
    inv3[0][0] = c00*id; inv3[0][1] = (m02*m21 - m01*m22)*id; inv3[0][2] = (m01*m12 - m02*m11)*id;
    inv3[1][0] = c01*id; inv3[1][1] = (m00*m22 - m02*m20)*id; inv3[1][2] = (m02*m10 - m00*m12)*id;
    inv3[2][0] = c02*id; inv3[2][1] = (m01*m20 - m00*m21)*id; inv3[2][2] = (m00*m11 - m01*m10)*id;

    double it[3];
    #pragma unroll
    for (int k = 0; k < 3; k++)
        it[k] = -(inv3[k][0]*t0 + inv3[k][1]*t1 + inv3[k][2]*t2);

    float Ps[4][4];
    combine_f32(proj + (size_t)(b*Vn + v) * 32, Ps);
    float* o = g_rt + (b*Vn + v) * 12;
    #pragma unroll
    for (int i = 0; i < 3; i++) {
        double r0 = 0, r1 = 0, r2 = 0, t = (double)Ps[i][3];
        #pragma unroll
        for (int k = 0; k < 3; k++) {
            double s = (double)Ps[i][k];
            r0 += s * inv3[k][0];
            r1 += s * inv3[k][1];
            r2 += s * inv3[k][2];
            t  += s * it[k];
        }
        o[i*3 + 0] = (float)r0;
        o[i*3 + 1] = (float)r1;
        o[i*3 + 2] = (float)r2;
        o[9 + i]   = (float)t;
    }
}

// ---------------------------------------------------------------------------
// Transpose+convert: feats [BV, C, HW] f32 -> g_fT [BV, HW, C] fp16.
// Block (0,0) additionally runs prep on lanes 0..7 (hidden under transpose).
// ---------------------------------------------------------------------------
__global__ void __launch_bounds__(256)
transpose_kernel(const float* __restrict__ feats, const float* __restrict__ proj) {
    __shared__ float tile[32][65];
    const int bv   = blockIdx.y;
    const int pix0 = blockIdx.x * 64;
    const int tid = threadIdx.x;
    const int tx = tid & 15;      // pixel-quad 0..15 (4 px each)
    const int ty = tid >> 4;      // 0..15

    const float* src = feats + (size_t)bv * (Cn*HWn);
    #pragma unroll
    for (int r = 0; r < 2; r++) {
        int ch = ty + 16*r;
        float4 v = *(const float4*)(src + (size_t)ch*HWn + pix0 + tx*4);
        tile[ch][tx*4 + 0] = v.x;
        tile[ch][tx*4 + 1] = v.y;
        tile[ch][tx*4 + 2] = v.z;
        tile[ch][tx*4 + 3] = v.w;
    }
    __syncthreads();

    const int p = tid >> 2;       // pixel 0..63
    const int q = tid & 3;        // channel-quarter
    __half2 h[4];
    #pragma unroll
    for (int k = 0; k < 4; k++) {
        int c = q*8 + 2*k;
        h[k] = __floats2half2_rn(tile[c][p], tile[c+1][p]);
    }
    uint4 pk = make_uint4(*(unsigned*)&h[0], *(unsigned*)&h[1],
                          *(unsigned*)&h[2], *(unsigned*)&h[3]);
    uint4* dst = (uint4*)(g_fT + ((size_t)bv*HWn + pix0) * 16);
    dst[p*4 + q] = pk;

    // fold prep into this launch: one warp of block (0,0), lanes 0..7
    if (blockIdx.x == 0 && blockIdx.y == 0 && tid < Bn*(Vn-1))
        prep_lane(proj, tid);
}

// ---------------------------------------------------------------------------
// Main kernel: thread = (b, pixel, cc); cc owns channels [cc*8, cc*8+8).
// half2 bilinear blend, f32 accumulation. Mask from weights.
// ---------------------------------------------------------------------------
__global__ void __launch_bounds__(256, 3)
hammer_kernel(const float* __restrict__ depthv,
              float* __restrict__ outv,
              float* __restrict__ outm)
{
    __shared__ float s_rt[Bn*Vn*12];
    const int t = threadIdx.x;
    if (t < Bn*Vn*12) s_rt[t] = g_rt[t];
    __syncthreads();

    const int gid = blockIdx.x*256 + t;
    const int cc  = gid & 3;
    const int pg  = gid >> 2;          // 0..Bn*HWn-1
    const int b   = pg / HWn;
    const int pix = pg - b*HWn;
    const float xf = (float)(pix % Wn);
    const float yf = (float)(pix / Wn);

    // depth for all 4 planes up front (independent loads -> MLP)
    float dep4[Dn];
    #pragma unroll
    for (int d = 0; d < Dn; d++)
        dep4[d] = __ldg(depthv + (b*Dn + d)*HWn + pix);

    // reference view: d-invariant, load once, convert to f32
    float rv[8];
    {
        uint4 ru = __ldg((const uint4*)(g_fT + ((size_t)(b*Vn)*HWn + pix)*16 + cc*4));
        const __half2* hp = (const __half2*)&ru;
        #pragma unroll
        for (int k = 0; k < 4; k++) {
            float2 a = __half22float2(hp[k]);
            rv[2*k]   = a.x;
            rv[2*k+1] = a.y;
        }
    }

    // per-view row dots (depth-independent)
    float Ar[4], Br[4], Cr[4];
    #pragma unroll
    for (int vi = 0; vi < 4; vi++) {
        const float* M = &s_rt[(b*Vn + vi + 1)*12];
        Ar[vi] = fmaf(M[0], xf, fmaf(M[1], yf, M[2]));
        Br[vi] = fmaf(M[3], xf, fmaf(M[4], yf, M[5]));
        Cr[vi] = fmaf(M[6], xf, fmaf(M[7], yf, M[8]));
    }

    int mcnt = 0;

    #pragma unroll 1
    for (int d = 0; d < Dn; d++) {
        const float dep = dep4[d];
        float s8[8], q8[8];
        #pragma unroll
        for (int j = 0; j < 8; j++) { s8[j] = rv[j]; q8[j] = rv[j]*rv[j]; }

        #pragma unroll
        for (int vi = 0; vi < 4; vi++) {
            const float* M = &s_rt[(b*Vn + vi + 1)*12];
            float pxv = fmaf(Ar[vi], dep, M[9]);
            float pyv = fmaf(Br[vi], dep, M[10]);
            float pzv = fmaf(Cr[vi], dep, M[11]);
            float rz = __frcp_rn(pzv);
            float gx = pxv * rz;
            float gy = pyv * rz;

            float fx0 = floorf(gx), fy0 = floorf(gy);
            float ax = gx - fx0,    ay = gy - fy0;
            int x0 = (int)fx0, y0 = (int)fy0;
            int x1 = x0 + 1,   y1 = y0 + 1;
            float wx0 = (x0 >= 0 && x0 < Wn) ? (1.f - ax) : 0.f;
            float wx1 = (x1 >= 0 && x1 < Wn) ? ax : 0.f;
            float wy0 = (y0 >= 0 && y0 < Hn) ? (1.f - ay) : 0.f;
            float wy1 = (y1 >= 0 && y1 < Hn) ? ay : 0.f;

            // mask: any corner weight nonzero <=> x-side and y-side both reachable
            if (((wx0 + wx1) * (wy0 + wy1)) != 0.f) mcnt++;

            int pb = min(max(x0, 0), Wn - 2);
            float wxA = (x0 == pb)     ? wx0 : ((x1 == pb)     ? wx1 : 0.f);
            float wxB = (x1 == pb + 1) ? wx1 : ((x0 == pb + 1) ? wx0 : 0.f);
            int y0c = min(max(y0, 0), Hn - 1);
            int y1c = min(max(y1, 0), Hn - 1);

            const int vbase = (b*Vn + vi + 1)*HWn;
            const __half2* r0 = g_fT + (size_t)(vbase + y0c*Wn + pb)*16 + cc*4;
            const __half2* r1 = g_fT + (size_t)(vbase + y1c*Wn + pb)*16 + cc*4;
            uint4 u00 = __ldg((const uint4*)r0);
            uint4 u01 = __ldg((const uint4*)(r0 + 16));
            uint4 u10 = __ldg((const uint4*)r1);
            uint4 u11 = __ldg((const uint4*)(r1 + 16));

            __half2 wxA2 = __float2half2_rn(wxA);
            __half2 wxB2 = __float2half2_rn(wxB);
            __half2 wy02 = __float2half2_rn(wy0);
            __half2 wy12 = __float2half2_rn(wy1);

            const __half2* h00 = (const __half2*)&u00;
            const __half2* h01 = (const __half2*)&u01;
            const __half2* h10 = (const __half2*)&u10;
            const __half2* h11 = (const __half2*)&u11;

            #pragma unroll
            for (int k = 0; k < 4; k++) {
                __half2 ra = __hfma2(wxB2, h01[k], __hmul2(wxA2, h00[k]));
                __half2 rb = __hfma2(wxB2, h11[k], __hmul2(wxA2, h10[k]));
                __half2 v2 = __hfma2(wy12, rb, __hmul2(wy02, ra));
                float2 vf = __half22float2(v2);
                s8[2*k]   += vf.x;
                s8[2*k+1] += vf.y;
                q8[2*k]   = fmaf(vf.x, vf.x, q8[2*k]);
                q8[2*k+1] = fmaf(vf.y, vf.y, q8[2*k+1]);
            }
        }

        const int ob = ((b*Cn + cc*8)*Dn + d)*HWn + pix;
        #pragma unroll
        for (int j = 0; j < 8; j++) {
            float e = s8[j] * 0.2f;
            outv[ob + j*(Dn*HWn)] = fmaf(q8[j], 0.2f, -e*e);
        }
    }

    if (cc == 0) outm[b*HWn + pix] = (float)mcnt;
}

// ---------------------------------------------------------------------------
// Launch
// ---------------------------------------------------------------------------
extern "C" void kernel_launch(void* const* d_in, const int* in_sizes, int n_in,
                              void* d_out, int out_size)
{
    const float* feats  = (const float*)d_in[0];
    const float* proj   = (const float*)d_in[1];
    const float* depthv = (const float*)d_in[2];

    float* outv = (float*)d_out;
    float* outm = outv + VAR_ELEMS;

    transpose_kernel<<<dim3(HWn/64, Bn*Vn), 256>>>(feats, proj);
    hammer_kernel<<<(Bn*HWn*4)/256, 256>>>(depthv, outv, outm);
}

// round 7
// speedup vs baseline: 3.1372x; 1.1156x over previous
#include <cuda_runtime.h>
#include <cuda_fp16.h>

#define Bn 2
#define Vn 5
#define Cn 32
#define Hn 256
#define Wn 320
#define Dn 4
#define HWn (Hn*Wn)
#define VAR_ELEMS (Bn*Cn*Dn*HWn)  // 20971520

// rot(9) + trans(3) per (b, v) for v=1..Vn-1
__device__ float g_rt[Bn*Vn*12];
// feats transposed to [B, V, H*W, C] in fp16 (channel-contiguous 64B pixel lines)
__device__ __half2 g_fT[(size_t)Bn*Vn*HWn*(Cn/2)];

// ---------------------------------------------------------------------------
// f32x2 packed-math helpers (Blackwell-only PTX; ptxas won't auto-emit these)
// ---------------------------------------------------------------------------
__device__ __forceinline__ unsigned long long pk2(float a, float b) {
    unsigned long long r;
    asm("mov.b64 %0, {%1, %2};" : "=l"(r) : "f"(a), "f"(b));
    return r;
}
__device__ __forceinline__ float2 upk2(unsigned long long v) {
    float2 r;
    asm("mov.b64 {%0, %1}, %2;" : "=f"(r.x), "=f"(r.y) : "l"(v));
    return r;
}
__device__ __forceinline__ unsigned long long mul2(unsigned long long a, unsigned long long b) {
    unsigned long long r;
    asm("mul.rn.f32x2 %0, %1, %2;" : "=l"(r) : "l"(a), "l"(b));
    return r;
}
__device__ __forceinline__ unsigned long long fma2(unsigned long long a, unsigned long long b,
                                                   unsigned long long c) {
    unsigned long long r;
    asm("fma.rn.f32x2 %0, %1, %2, %3;" : "=l"(r) : "l"(a), "l"(b), "l"(c));
    return r;
}
__device__ __forceinline__ void acc2(unsigned long long& s, unsigned long long& q, float2 v) {
    unsigned long long pv = pk2(v.x, v.y);
    asm("add.rn.f32x2 %0, %0, %1;" : "+l"(s) : "l"(pv));
    asm("fma.rn.f32x2 %0, %1, %1, %0;" : "+l"(q) : "l"(pv));
}

// ---------------------------------------------------------------------------
// Prep (device-side, lane-parallel): combine projections, structured inverse
// ---------------------------------------------------------------------------
__device__ __forceinline__ void combine_f32(const float* p, float M[4][4]) {
    const float* E = p;
    const float* K = p + 16;
    #pragma unroll
    for (int i = 0; i < 4; i++)
        #pragma unroll
        for (int j = 0; j < 4; j++)
            M[i][j] = E[i*4 + j];
    #pragma unroll
    for (int i = 0; i < 3; i++)
        #pragma unroll
        for (int j = 0; j < 4; j++) {
            float s = 0.f;
            #pragma unroll
            for (int k = 0; k < 3; k++) s += K[i*4 + k] * E[k*4 + j];
            M[i][j] = s;
        }
}

__device__ void prep_lane(const float* __restrict__ proj, int l) {
    const int b = l / (Vn - 1);
    const int v = (l % (Vn - 1)) + 1;

    float Pr[4][4];
    combine_f32(proj + (size_t)(b*Vn + 0) * 32, Pr);

    double m00 = Pr[0][0], m01 = Pr[0][1], m02 = Pr[0][2];
    double m10 = Pr[1][0], m11 = Pr[1][1], m12 = Pr[1][2];
    double m20 = Pr[2][0], m21 = Pr[2][1], m22 = Pr[2][2];
    double t0  = Pr[0][3], t1  = Pr[1][3], t2  = Pr[2][3];

    double c00 = m11*m22 - m12*m21;
    double c01 = m12*m20 - m10*m22;
    double c02 = m10*m21 - m11*m20;
    double det = m00*c00 + m01*c01 + m02*c02;
    double id  = 1.0 / det;

    double inv3[3][3];
    inv3[0][0] = c00*id; inv3[0][1] = (m02*m21 - m01*m22)*id; inv3[0][2] = (m01*m12 - m02*m11)*id;
    inv3[1][0] = c01*id; inv3[1][1] = (m00*m22 - m02*m20)*id; inv3[1][2] = (m02*m10 - m00*m12)*id;
    inv3[2][0] = c02*id; inv3[2][1] = (m01*m20 - m00*m21)*id; inv3[2][2] = (m00*m11 - m01*m10)*id;

    double it[3];
    #pragma unroll
    for (int k = 0; k < 3; k++)
        it[k] = -(inv3[k][0]*t0 + inv3[k][1]*t1 + inv3[k][2]*t2);

    float Ps[4][4];
    combine_f32(proj + (size_t)(b*Vn + v) * 32, Ps);
    float* o = g_rt + (b*Vn + v) * 12;
    #pragma unroll
    for (int i = 0; i < 3; i++) {
        double r0 = 0, r1 = 0, r2 = 0, t = (double)Ps[i][3];
        #pragma unroll
        for (int k = 0; k < 3; k++) {
            double s = (double)Ps[i][k];
            r0 += s * inv3[k][0];
            r1 += s * inv3[k][1];
            r2 += s * inv3[k][2];
            t  += s * it[k];
        }
        o[i*3 + 0] = (float)r0;
        o[i*3 + 1] = (float)r1;
        o[i*3 + 2] = (float)r2;
        o[9 + i]   = (float)t;
    }
}

// ---------------------------------------------------------------------------
// Transpose+convert: feats [BV, C, HW] f32 -> g_fT [BV, HW, C] fp16.
// Block (0,0) additionally runs prep on lanes 0..7 (hidden under transpose).
// ---------------------------------------------------------------------------
__global__ void __launch_bounds__(256)
transpose_kernel(const float* __restrict__ feats, const float* __restrict__ proj) {
    __shared__ float tile[32][65];
    const int bv   = blockIdx.y;
    const int pix0 = blockIdx.x * 64;
    const int tid = threadIdx.x;
    const int tx = tid & 15;
    const int ty = tid >> 4;

    const float* src = feats + (size_t)bv * (Cn*HWn);
    #pragma unroll
    for (int r = 0; r < 2; r++) {
        int ch = ty + 16*r;
        float4 v = *(const float4*)(src + (size_t)ch*HWn + pix0 + tx*4);
        tile[ch][tx*4 + 0] = v.x;
        tile[ch][tx*4 + 1] = v.y;
        tile[ch][tx*4 + 2] = v.z;
        tile[ch][tx*4 + 3] = v.w;
    }
    __syncthreads();

    const int p = tid >> 2;
    const int q = tid & 3;
    __half2 h[4];
    #pragma unroll
    for (int k = 0; k < 4; k++) {
        int c = q*8 + 2*k;
        h[k] = __floats2half2_rn(tile[c][p], tile[c+1][p]);
    }
    uint4 pkv = make_uint4(*(unsigned*)&h[0], *(unsigned*)&h[1],
                           *(unsigned*)&h[2], *(unsigned*)&h[3]);
    uint4* dst = (uint4*)(g_fT + ((size_t)bv*HWn + pix0) * 16);
    dst[p*4 + q] = pkv;

    if (blockIdx.x == 0 && blockIdx.y == 0 && tid < Bn*(Vn-1))
        prep_lane(proj, tid);
}

// ---------------------------------------------------------------------------
// Main kernel: thread = (b, pixel, cc); cc owns channels [cc*8, cc*8+8).
// Lane-split coords: lane cc computes view cc+1's warp params, then the 4
// lanes of a pixel exchange params via width-4 shuffles. f32x2 accumulation.
// ---------------------------------------------------------------------------
__global__ void __launch_bounds__(256, 3)
hammer_kernel(const float* __restrict__ depthv,
              float* __restrict__ outv,
              float* __restrict__ outm)
{
    __shared__ float s_rt[Bn*Vn*12];
    const int t = threadIdx.x;
    if (t < Bn*Vn*12) s_rt[t] = g_rt[t];
    __syncthreads();

    const int gid = blockIdx.x*256 + t;
    const int cc  = gid & 3;
    const int pg  = gid >> 2;          // 0..Bn*HWn-1
    const int b   = pg / HWn;
    const int pix = pg - b*HWn;
    const float xf = (float)(pix % Wn);
    const float yf = (float)(pix / Wn);

    // depth for all 4 planes up front
    float dep4[Dn];
    #pragma unroll
    for (int d = 0; d < Dn; d++)
        dep4[d] = __ldg(depthv + (b*Dn + d)*HWn + pix);

    // reference view (d-invariant): keep packed f32x2 init values
    unsigned long long rvs[4], rvq[4];
    {
        uint4 ru = __ldg((const uint4*)(g_fT + ((size_t)(b*Vn)*HWn + pix)*16 + cc*4));
        const __half2* hp = (const __half2*)&ru;
        #pragma unroll
        for (int k = 0; k < 4; k++) {
            float2 a = __half22float2(hp[k]);
            rvs[k] = pk2(a.x, a.y);
            rvq[k] = pk2(a.x*a.x, a.y*a.y);
        }
    }

    // this lane's view (vi = cc): row dots + translation, hoisted
    const float* M = &s_rt[(b*Vn + cc + 1)*12];
    const float Ar = fmaf(M[0], xf, fmaf(M[1], yf, M[2]));
    const float Br = fmaf(M[3], xf, fmaf(M[4], yf, M[5]));
    const float Cr = fmaf(M[6], xf, fmaf(M[7], yf, M[8]));
    const float T9 = M[9], T10 = M[10], T11 = M[11];
    const int   vbase_mine = (b*Vn + cc + 1)*HWn;

    const unsigned long long C02 = pk2( 0.2f,  0.2f);
    const unsigned long long CN2 = pk2(-0.2f, -0.2f);

    int mcnt = 0;

    #pragma unroll 1
    for (int d = 0; d < Dn; d++) {
        const float dep = dep4[d];

        // ---- my view's warp params ----
        float pxv = fmaf(Ar, dep, T9);
        float pyv = fmaf(Br, dep, T10);
        float pzv = fmaf(Cr, dep, T11);
        float rz = __frcp_rn(pzv);
        float gx = pxv * rz;
        float gy = pyv * rz;

        float fx0 = floorf(gx), fy0 = floorf(gy);
        float ax = gx - fx0,    ay = gy - fy0;
        int x0 = (int)fx0, y0 = (int)fy0;
        int x1 = x0 + 1,   y1 = y0 + 1;
        float wx0 = (x0 >= 0 && x0 < Wn) ? (1.f - ax) : 0.f;
        float wx1 = (x1 >= 0 && x1 < Wn) ? ax : 0.f;
        float wy0 = (y0 >= 0 && y0 < Hn) ? (1.f - ay) : 0.f;
        float wy1 = (y1 >= 0 && y1 < Hn) ? ay : 0.f;

        int valid = (((wx0 + wx1) * (wy0 + wy1)) != 0.f) ? 1 : 0;

        int pb = min(max(x0, 0), Wn - 2);
        float wxA = (x0 == pb)     ? wx0 : ((x1 == pb)     ? wx1 : 0.f);
        float wxB = (x1 == pb + 1) ? wx1 : ((x0 == pb + 1) ? wx0 : 0.f);
        int y0c = min(max(y0, 0), Hn - 1);
        int y1c = min(max(y1, 0), Hn - 1);

        __half2 wxh = __floats2half2_rn(wxA, wxB);
        __half2 wyh = __floats2half2_rn(wy0, wy1);
        unsigned wxu = *(unsigned*)&wxh;
        unsigned wyu = *(unsigned*)&wyh;
        int moff0 = (vbase_mine + y0c*Wn + pb)*16;   // half2 units, cc term added by receiver
        int moff1 = (vbase_mine + y1c*Wn + pb)*16;

        // mask: sum validity over the 4 views (4-lane group)
        valid += __shfl_xor_sync(0xffffffffu, valid, 1, 4);
        valid += __shfl_xor_sync(0xffffffffu, valid, 2, 4);
        mcnt += valid;

        unsigned long long s2[4], q2[4];
        #pragma unroll
        for (int k = 0; k < 4; k++) { s2[k] = rvs[k]; q2[k] = rvq[k]; }

        #pragma unroll
        for (int vi = 0; vi < 4; vi++) {
            int o0       = __shfl_sync(0xffffffffu, moff0, vi, 4);
            int o1       = __shfl_sync(0xffffffffu, moff1, vi, 4);
            unsigned wxb = __shfl_sync(0xffffffffu, wxu,   vi, 4);
            unsigned wyb = __shfl_sync(0xffffffffu, wyu,   vi, 4);
            __half2 wxv = *(__half2*)&wxb;
            __half2 wyv = *(__half2*)&wyb;
            __half2 wxA2 = __half2half2(__low2half(wxv));
            __half2 wxB2 = __half2half2(__high2half(wxv));
            __half2 wy02 = __half2half2(__low2half(wyv));
            __half2 wy12 = __half2half2(__high2half(wyv));

            const __half2* r0 = g_fT + o0 + cc*4;
            const __half2* r1 = g_fT + o1 + cc*4;
            uint4 u00 = __ldg((const uint4*)r0);
            uint4 u01 = __ldg((const uint4*)(r0 + 16));
            uint4 u10 = __ldg((const uint4*)r1);
            uint4 u11 = __ldg((const uint4*)(r1 + 16));

            const __half2* h00 = (const __half2*)&u00;
            const __half2* h01 = (const __half2*)&u01;
            const __half2* h10 = (const __half2*)&u10;
            const __half2* h11 = (const __half2*)&u11;

            #pragma unroll
            for (int k = 0; k < 4; k++) {
                __half2 ra = __hfma2(wxB2, h01[k], __hmul2(wxA2, h00[k]));
                __half2 rb = __hfma2(wxB2, h11[k], __hmul2(wxA2, h10[k]));
                __half2 v2 = __hfma2(wy12, rb, __hmul2(wy02, ra));
                acc2(s2[k], q2[k], __half22float2(v2));
            }
        }

        const int ob = ((b*Cn + cc*8)*Dn + d)*HWn + pix;
        #pragma unroll
        for (int k = 0; k < 4; k++) {
            // var = q*0.2 - (s*0.2)^2 = fma(s*0.2, s*(-0.2), q*0.2)
            unsigned long long u  = mul2(s2[k], C02);
            unsigned long long un = mul2(s2[k], CN2);
            unsigned long long qc = mul2(q2[k], C02);
            float2 r = upk2(fma2(u, un, qc));
            outv[ob + (2*k)  *(Dn*HWn)] = r.x;
            outv[ob + (2*k+1)*(Dn*HWn)] = r.y;
        }
    }

    if (cc == 0) outm[b*HWn + pix] = (float)mcnt;
}

// ---------------------------------------------------------------------------
// Launch
// ---------------------------------------------------------------------------
extern "C" void kernel_launch(void* const* d_in, const int* in_sizes, int n_in,
                              void* d_out, int out_size)
{
    const float* feats  = (const float*)d_in[0];
    const float* proj   = (const float*)d_in[1];
    const float* depthv = (const float*)d_in[2];

    float* outv = (float*)d_out;
    float* outm = outv + VAR_ELEMS;

    transpose_kernel<<<dim3(HWn/64, Bn*Vn), 256>>>(feats, proj);
    hammer_kernel<<<(Bn*HWn*4)/256, 256>>>(depthv, outv, outm);
}

// round 8
// speedup vs baseline: 3.2032x; 1.0210x over previous
#include <cuda_runtime.h>
#include <cuda_fp16.h>

#define Bn 2
#define Vn 5
#define Cn 32
#define Hn 256
#define Wn 320
#define Dn 4
#define HWn (Hn*Wn)
#define VAR_ELEMS (Bn*Cn*Dn*HWn)  // 20971520

// rot(9) + trans(3) per (b, v) for v=1..Vn-1
__device__ float g_rt[Bn*Vn*12];
// feats transposed to [B, V, H*W, C] in fp16 (channel-contiguous 64B pixel lines)
__device__ __half2 g_fT[(size_t)Bn*Vn*HWn*(Cn/2)];

// ---------------------------------------------------------------------------
// f32x2 packed-math helpers (Blackwell-only PTX; ptxas won't auto-emit these)
// ---------------------------------------------------------------------------
__device__ __forceinline__ unsigned long long pk2(float a, float b) {
    unsigned long long r;
    asm("mov.b64 %0, {%1, %2};" : "=l"(r) : "f"(a), "f"(b));
    return r;
}
__device__ __forceinline__ float2 upk2(unsigned long long v) {
    float2 r;
    asm("mov.b64 {%0, %1}, %2;" : "=f"(r.x), "=f"(r.y) : "l"(v));
    return r;
}
__device__ __forceinline__ unsigned long long mul2(unsigned long long a, unsigned long long b) {
    unsigned long long r;
    asm("mul.rn.f32x2 %0, %1, %2;" : "=l"(r) : "l"(a), "l"(b));
    return r;
}
__device__ __forceinline__ unsigned long long fma2(unsigned long long a, unsigned long long b,
                                                   unsigned long long c) {
    unsigned long long r;
    asm("fma.rn.f32x2 %0, %1, %2, %3;" : "=l"(r) : "l"(a), "l"(b), "l"(c));
    return r;
}
__device__ __forceinline__ void acc2(unsigned long long& s, unsigned long long& q, float2 v) {
    unsigned long long pv = pk2(v.x, v.y);
    asm("add.rn.f32x2 %0, %0, %1;" : "+l"(s) : "l"(pv));
    asm("fma.rn.f32x2 %0, %1, %1, %0;" : "+l"(q) : "l"(pv));
}

// ---------------------------------------------------------------------------
// Prep (device-side, lane-parallel): combine projections, structured inverse
// ---------------------------------------------------------------------------
__device__ __forceinline__ void combine_f32(const float* p, float M[4][4]) {
    const float* E = p;
    const float* K = p + 16;
    #pragma unroll
    for (int i = 0; i < 4; i++)
        #pragma unroll
        for (int j = 0; j < 4; j++)
            M[i][j] = E[i*4 + j];
    #pragma unroll
    for (int i = 0; i < 3; i++)
        #pragma unroll
        for (int j = 0; j < 4; j++) {
            float s = 0.f;
            #pragma unroll
            for (int k = 0; k < 3; k++) s += K[i*4 + k] * E[k*4 + j];
            M[i][j] = s;
        }
}

__device__ void prep_lane(const float* __restrict__ proj, int l) {
    const int b = l / (Vn - 1);
    const int v = (l % (Vn - 1)) + 1;

    float Pr[4][4];
    combine_f32(proj + (size_t)(b*Vn + 0) * 32, Pr);

    double m00 = Pr[0][0], m01 = Pr[0][1], m02 = Pr[0][2];
    double m10 = Pr[1][0], m11 = Pr[1][1], m12 = Pr[1][2];
    double m20 = Pr[2][0], m21 = Pr[2][1], m22 = Pr[2][2];
    double t0  = Pr[0][3], t1  = Pr[1][3], t2  = Pr[2][3];

    double c00 = m11*m22 - m12*m21;
    double c01 = m12*m20 - m10*m22;
    double c02 = m10*m21 - m11*m20;
    double det = m00*c00 + m01*c01 + m02*c02;
    double id  = 1.0 / det;

    double inv3[3][3];
    inv3[0][0] = c00*id; inv3[0][1] = (m02*m21 - m01*m22)*id; inv3[0][2] = (m01*m12 - m02*m11)*id;
    inv3[1][0] = c01*id; inv3[1][1] = (m00*m22 - m02*m20)*id; inv3[1][2] = (m02*m10 - m00*m12)*id;
    inv3[2][0] = c02*id; inv3[2][1] = (m01*m20 - m00*m21)*id; inv3[2][2] = (m00*m11 - m01*m10)*id;

    double it[3];
    #pragma unroll
    for (int k = 0; k < 3; k++)
        it[k] = -(inv3[k][0]*t0 + inv3[k][1]*t1 + inv3[k][2]*t2);

    float Ps[4][4];
    combine_f32(proj + (size_t)(b*Vn + v) * 32, Ps);
    float* o = g_rt + (b*Vn + v) * 12;
    #pragma unroll
    for (int i = 0; i < 3; i++) {
        double r0 = 0, r1 = 0, r2 = 0, t = (double)Ps[i][3];
        #pragma unroll
        for (int k = 0; k < 3; k++) {
            double s = (double)Ps[i][k];
            r0 += s * inv3[k][0];
            r1 += s * inv3[k][1];
            r2 += s * inv3[k][2];
            t  += s * it[k];
        }
        o[i*3 + 0] = (float)r0;
        o[i*3 + 1] = (float)r1;
        o[i*3 + 2] = (float)r2;
        o[9 + i]   = (float)t;
    }
}

// ---------------------------------------------------------------------------
// Transpose+convert: feats [BV, C, HW] f32 -> g_fT [BV, HW, C] fp16.
// Block (0,0) additionally runs prep on lanes 0..7 (hidden under transpose).
// ---------------------------------------------------------------------------
__global__ void __launch_bounds__(256)
transpose_kernel(const float* __restrict__ feats, const float* __restrict__ proj) {
    __shared__ float tile[32][65];
    const int bv   = blockIdx.y;
    const int pix0 = blockIdx.x * 64;
    const int tid = threadIdx.x;
    const int tx = tid & 15;
    const int ty = tid >> 4;

    const float* src = feats + (size_t)bv * (Cn*HWn);
    #pragma unroll
    for (int r = 0; r < 2; r++) {
        int ch = ty + 16*r;
        float4 v = *(const float4*)(src + (size_t)ch*HWn + pix0 + tx*4);
        tile[ch][tx*4 + 0] = v.x;
        tile[ch][tx*4 + 1] = v.y;
        tile[ch][tx*4 + 2] = v.z;
        tile[ch][tx*4 + 3] = v.w;
    }
    __syncthreads();

    const int p = tid >> 2;
    const int q = tid & 3;
    __half2 h[4];
    #pragma unroll
    for (int k = 0; k < 4; k++) {
        int c = q*8 + 2*k;
        h[k] = __floats2half2_rn(tile[c][p], tile[c+1][p]);
    }
    uint4 pkv = make_uint4(*(unsigned*)&h[0], *(unsigned*)&h[1],
                           *(unsigned*)&h[2], *(unsigned*)&h[3]);
    uint4* dst = (uint4*)(g_fT + ((size_t)bv*HWn + pix0) * 16);
    dst[p*4 + q] = pkv;

    if (blockIdx.x == 0 && blockIdx.y == 0 && tid < Bn*(Vn-1))
        prep_lane(proj, tid);
}

// ---------------------------------------------------------------------------
// Main kernel: thread = (b, pixel, cc); cc owns channels [cc*8, cc*8+8).
// Lane-split coords + width-4 shuffle exchange; f32x2 accumulation.
// 64-reg budget (4 blocks/SM) -> ref q-init recomputed per d.
// ---------------------------------------------------------------------------
__global__ void __launch_bounds__(256, 4)
hammer_kernel(const float* __restrict__ depthv,
              float* __restrict__ outv,
              float* __restrict__ outm)
{
    __shared__ float s_rt[Bn*Vn*12];
    const int t = threadIdx.x;
    if (t < Bn*Vn*12) s_rt[t] = g_rt[t];
    __syncthreads();

    const int gid = blockIdx.x*256 + t;
    const int cc  = gid & 3;
    const int pg  = gid >> 2;          // 0..Bn*HWn-1
    const int b   = pg / HWn;
    const int pix = pg - b*HWn;
    const float xf = (float)(pix % Wn);
    const float yf = (float)(pix / Wn);

    // depth for all 4 planes up front
    float dep4[Dn];
    #pragma unroll
    for (int d = 0; d < Dn; d++)
        dep4[d] = __ldg(depthv + (b*Dn + d)*HWn + pix);

    // reference view (d-invariant): packed f32x2 values only (q recomputed per d)
    unsigned long long rvs[4];
    {
        uint4 ru = __ldg((const uint4*)(g_fT + ((size_t)(b*Vn)*HWn + pix)*16 + cc*4));
        const __half2* hp = (const __half2*)&ru;
        #pragma unroll
        for (int k = 0; k < 4; k++) {
            float2 a = __half22float2(hp[k]);
            rvs[k] = pk2(a.x, a.y);
        }
    }

    // this lane's view (vi = cc): row dots + translation, hoisted
    const float* M = &s_rt[(b*Vn + cc + 1)*12];
    const float Ar = fmaf(M[0], xf, fmaf(M[1], yf, M[2]));
    const float Br = fmaf(M[3], xf, fmaf(M[4], yf, M[5]));
    const float Cr = fmaf(M[6], xf, fmaf(M[7], yf, M[8]));
    const float T9 = M[9], T10 = M[10], T11 = M[11];
    const int   vbase_mine = (b*Vn + cc + 1)*HWn;

    const unsigned long long C02 = pk2( 0.2f,  0.2f);
    const unsigned long long CN2 = pk2(-0.2f, -0.2f);

    int mcnt = 0;

    #pragma unroll 1
    for (int d = 0; d < Dn; d++) {
        const float dep = dep4[d];

        // ---- my view's warp params ----
        float pxv = fmaf(Ar, dep, T9);
        float pyv = fmaf(Br, dep, T10);
        float pzv = fmaf(Cr, dep, T11);
        float rz = __frcp_rn(pzv);
        float gx = pxv * rz;
        float gy = pyv * rz;

        float fx0 = floorf(gx), fy0 = floorf(gy);
        float ax = gx - fx0,    ay = gy - fy0;
        int x0 = (int)fx0, y0 = (int)fy0;
        int x1 = x0 + 1,   y1 = y0 + 1;
        float wx0 = (x0 >= 0 && x0 < Wn) ? (1.f - ax) : 0.f;
        float wx1 = (x1 >= 0 && x1 < Wn) ? ax : 0.f;
        float wy0 = (y0 >= 0 && y0 < Hn) ? (1.f - ay) : 0.f;
        float wy1 = (y1 >= 0 && y1 < Hn) ? ay : 0.f;

        int valid = (((wx0 + wx1) * (wy0 + wy1)) != 0.f) ? 1 : 0;

        int pb = min(max(x0, 0), Wn - 2);
        float wxA = (x0 == pb)     ? wx0 : ((x1 == pb)     ? wx1 : 0.f);
        float wxB = (x1 == pb + 1) ? wx1 : ((x0 == pb + 1) ? wx0 : 0.f);
        int y0c = min(max(y0, 0), Hn - 1);
        int y1c = min(max(y1, 0), Hn - 1);

        __half2 wxh = __floats2half2_rn(wxA, wxB);
        __half2 wyh = __floats2half2_rn(wy0, wy1);
        unsigned wxu = *(unsigned*)&wxh;
        unsigned wyu = *(unsigned*)&wyh;
        // offsets in half2 units; cc*4 term added here once (same for all lanes)
        int moff0 = (vbase_mine + y0c*Wn + pb)*16 + cc*4;
        int moff1 = (vbase_mine + y1c*Wn + pb)*16 + cc*4;

        // mask: sum validity over the 4 views (4-lane group)
        valid += __shfl_xor_sync(0xffffffffu, valid, 1, 4);
        valid += __shfl_xor_sync(0xffffffffu, valid, 2, 4);
        mcnt += valid;

        unsigned long long s2[4], q2[4];
        #pragma unroll
        for (int k = 0; k < 4; k++) {
            s2[k] = rvs[k];
            q2[k] = mul2(rvs[k], rvs[k]);
        }

        #pragma unroll
        for (int vi = 0; vi < 4; vi++) {
            // broadcaster lane vi already folded its own cc*4; strip/re-add is
            // avoided by exchanging the *base* (moff - cc*4 is lane-invariant):
            int o0       = __shfl_sync(0xffffffffu, moff0 - cc*4, vi, 4) + cc*4;
            int o1       = __shfl_sync(0xffffffffu, moff1 - cc*4, vi, 4) + cc*4;
            unsigned wxb = __shfl_sync(0xffffffffu, wxu,          vi, 4);
            unsigned wyb = __shfl_sync(0xffffffffu, wyu,          vi, 4);
            __half2 wxv = *(__half2*)&wxb;
            __half2 wyv = *(__half2*)&wyb;
            __half2 wxA2 = __half2half2(__low2half(wxv));
            __half2 wxB2 = __half2half2(__high2half(wxv));
            __half2 wy02 = __half2half2(__low2half(wyv));
            __half2 wy12 = __half2half2(__high2half(wyv));

            const __half2* r0 = g_fT + o0;
            const __half2* r1 = g_fT + o1;
            uint4 u00 = __ldg((const uint4*)r0);
            uint4 u01 = __ldg((const uint4*)(r0 + 16));
            uint4 u10 = __ldg((const uint4*)r1);
            uint4 u11 = __ldg((const uint4*)(r1 + 16));

            const __half2* h00 = (const __half2*)&u00;
            const __half2* h01 = (const __half2*)&u01;
            const __half2* h10 = (const __half2*)&u10;
            const __half2* h11 = (const __half2*)&u11;

            #pragma unroll
            for (int k = 0; k < 4; k++) {
                __half2 ra = __hfma2(wxB2, h01[k], __hmul2(wxA2, h00[k]));
                __half2 rb = __hfma2(wxB2, h11[k], __hmul2(wxA2, h10[k]));
                __half2 v2 = __hfma2(wy12, rb, __hmul2(wy02, ra));
                acc2(s2[k], q2[k], __half22float2(v2));
            }
        }

        const int ob = ((b*Cn + cc*8)*Dn + d)*HWn + pix;
        #pragma unroll
        for (int k = 0; k < 4; k++) {
            // var = q*0.2 - (s*0.2)^2 = fma(s*0.2, s*(-0.2), q*0.2)
            unsigned long long u  = mul2(s2[k], C02);
            unsigned long long un = mul2(s2[k], CN2);
            unsigned long long qc = mul2(q2[k], C02);
            float2 r = upk2(fma2(u, un, qc));
            outv[ob + (2*k)  *(Dn*HWn)] = r.x;
            outv[ob + (2*k+1)*(Dn*HWn)] = r.y;
        }
    }

    if (cc == 0) outm[b*HWn + pix] = (float)mcnt;
}

// ---------------------------------------------------------------------------
// Launch
// ---------------------------------------------------------------------------
extern "C" void kernel_launch(void* const* d_in, const int* in_sizes, int n_in,
                              void* d_out, int out_size)
{
    const float* feats  = (const float*)d_in[0];
    const float* proj   = (const float*)d_in[1];
    const float* depthv = (const float*)d_in[2];

    float* outv = (float*)d_out;
    float* outm = outv + VAR_ELEMS;

    transpose_kernel<<<dim3(HWn/64, Bn*Vn), 256>>>(feats, proj);
    hammer_kernel<<<(Bn*HWn*4)/256, 256>>>(depthv, outv, outm);
}